// round 9
// baseline (speedup 1.0000x reference)
#include <cuda_runtime.h>
#include <math.h>

#define NL 24
#define D 1024
#define NH 16
#define SS 4096
#define NBLK 148
#define NCOMP 64
#define NCOPY (NBLK - NCOMP)
#define NHEAD_OUT 47   // 32 + 7 + 8

// -------- device scratch (allocation-free) --------
__device__ __align__(16) float g_q[D];
__device__ __align__(16) float g_knew[D];
__device__ __align__(16) float g_vnew[D];
__device__ __align__(16) float g_x[D];
__device__ __align__(16) float g_xmid[D];
__device__ __align__(16) float g_attnout[D];
__device__ __align__(16) float g_h1[D];
__device__ __align__(16) float g_ffout[D];
__device__ __align__(16) float g_avp[NCOMP * D];   // per-chunk unnormalized AV partials
__device__ float g_s[NH * NCOMP];                  // per (head, chunk) sum of exp
__device__ unsigned g_count = 0;
__device__ volatile unsigned g_gen = 0;

// -------- software grid barrier among NCOMP blocks --------
__device__ __forceinline__ void comp_sync() {
    __syncthreads();
    if (threadIdx.x == 0) {
        unsigned g = g_gen;
        __threadfence();
        if (atomicAdd(&g_count, 1u) == NCOMP - 1) {
            g_count = 0;
            __threadfence();
            g_gen = g + 1;
        } else {
            unsigned ns = 8;
            while (g_gen == g) { __nanosleep(ns); if (ns < 256) ns <<= 1; }
        }
        __threadfence();
    }
    __syncthreads();
}

// -------- reductions (1024 threads, 32 warps) --------
__device__ __forceinline__ float warpReduceSum(float v) {
#pragma unroll
    for (int o = 16; o > 0; o >>= 1) v += __shfl_down_sync(0xffffffffu, v, o);
    return v;
}
__device__ __forceinline__ float blockReduceSum32(float v, float* red) {
    int tid = threadIdx.x;
    v = warpReduceSum(v);
    if ((tid & 31) == 0) red[tid >> 5] = v;
    __syncthreads();
    if (tid < 32) {
        float t = red[tid];
        t = warpReduceSum(t);
        if (tid == 0) red[0] = t;
    }
    __syncthreads();
    float r = red[0];
    __syncthreads();
    return r;
}
__device__ __forceinline__ float ln_elem(float a, float sc, float bi, float* red) {
    float sum = blockReduceSum32(a, red);
    float sq  = blockReduceSum32(a * a, red);
    float mean = sum * (1.f / D);
    float inv = rsqrtf(sq * (1.f / D) - mean * mean + 1e-6f);
    return (a - mean) * inv * sc + bi;
}

// GEMV unit: 8 output cols (jbase..jbase+7), 1024 threads.
// Thread (jq = tid&1, rr = tid>>1): rows 2rr, 2rr+1 -> 2 LDG.128.
// One __syncthreads; caller alternates red4 buffers between units.
__device__ __forceinline__ float gemv_unit(const float* __restrict__ W,
                                           const float* xs, int jbase,
                                           float4* red4buf) {
    int tid = threadIdx.x;
    int jq = tid & 1, rr = tid >> 1;
    const float4* Wp = (const float4*)W + ((size_t)(rr << 1)) * 256 + (jbase >> 2) + jq;
    float4 w0 = Wp[0];
    float4 w1 = Wp[256];
    float x0 = xs[rr << 1], x1 = xs[(rr << 1) + 1];
    float4 a;
    a.x = x0 * w0.x + x1 * w1.x;
    a.y = x0 * w0.y + x1 * w1.y;
    a.z = x0 * w0.z + x1 * w1.z;
    a.w = x0 * w0.w + x1 * w1.w;
#pragma unroll
    for (int o = 16; o >= 2; o >>= 1) {   // even offsets preserve jq parity
        a.x += __shfl_down_sync(0xffffffffu, a.x, o);
        a.y += __shfl_down_sync(0xffffffffu, a.y, o);
        a.z += __shfl_down_sync(0xffffffffu, a.z, o);
        a.w += __shfl_down_sync(0xffffffffu, a.w, o);
    }
    if ((tid & 31) < 2) red4buf[((tid >> 5) << 1) | (tid & 1)] = a;
    __syncthreads();
    float v = 0.f;
    if (tid < 8) {
        int jqq = tid >> 2, comp = tid & 3;
#pragma unroll
        for (int w = 0; w < 32; ++w) {
            float4 r = red4buf[(w << 1) | jqq];
            v += (comp == 0) ? r.x : (comp == 1) ? r.y : (comp == 2) ? r.z : r.w;
        }
    }
    return v;
}

__global__ void __launch_bounds__(1024, 1) mono_kernel(
    const float* __restrict__ xin, const float* __restrict__ oldc,
    const float* __restrict__ Wv, const float* __restrict__ bv,
    const float* __restrict__ Wq, const float* __restrict__ bq,
    const float* __restrict__ Wk, const float* __restrict__ bk,
    const float* __restrict__ Wo, const float* __restrict__ bo,
    const float* __restrict__ ln1s, const float* __restrict__ ln1b,
    const float* __restrict__ ln2s, const float* __restrict__ ln2b,
    const float* __restrict__ Wf1, const float* __restrict__ bf1,
    const float* __restrict__ Wf2, const float* __restrict__ bf2,
    const float* __restrict__ Wpi, const float* __restrict__ bpi,
    const float* __restrict__ Wvh, const float* __restrict__ bvh,
    const float* __restrict__ Wc,  const float* __restrict__ bc,
    float* __restrict__ out, float* __restrict__ newc) {
    int bid = blockIdx.x;
    int tid = threadIdx.x;

    if (bid >= NCOMP) {
        // ---- background copy blocks: shift all layers' K/V planes ----
        int cb = bid - NCOMP;
        const long TOT = (long)NL * 2 * (SS - 1);     // 196560 rows
        long per = (TOT + NCOPY - 1) / NCOPY;
        long r0 = (long)cb * per;
        long r1 = r0 + per; if (r1 > TOT) r1 = TOT;
        int rr = tid >> 8, e = tid & 255;
        const float4* o4 = (const float4*)oldc;
        for (long base = r0; base < r1; base += 16) {
#pragma unroll
            for (int k = 0; k < 4; ++k) {
                long row = base + (k << 2) + rr;
                if (row < r1) {
                    long l  = row / (2 * (SS - 1));
                    long rem = row - l * (2 * (SS - 1));
                    long pl = rem / (SS - 1);
                    long s  = rem - pl * (SS - 1);
                    long prow = (l * 2 + pl) * SS + s;
                    float4 v = __ldcs(&o4[(prow + 1) * 256 + e]);
                    float* dst = newc + prow * (long)D + (e << 2);
                    __stcs(dst + 0, v.x); __stcs(dst + 1, v.y);
                    __stcs(dst + 2, v.z); __stcs(dst + 3, v.w);
                }
            }
        }
        return;
    }

    // ---- compute blocks ----
    __shared__ float xs[D];
    __shared__ float red[32];
    __shared__ float4 red4[2][64];
    __shared__ int flags[2][32];
    __shared__ float sbuf[4][16];
    __shared__ float4 accbuf[4][256];

    for (int l = 0; l < NL; ++l) {
        size_t mo = (size_t)l * D * D;
        size_t vo = (size_t)l * D;
        size_t vplane = (size_t)(l * 2) * SS;        // row base of v plane
        size_t kplane = vplane + SS;

        // ===== Phase A: layer input (LN2 of prev or x) + q/k/v GEMVs =====
        if (l == 0) {
            xs[tid] = xin[tid];
        } else {
            float a = g_xmid[tid] + g_ffout[tid];
            xs[tid] = ln_elem(a, ln2s[vo - D + tid], ln2b[vo - D + tid], red);
        }
        __syncthreads();
        if (bid == 0) g_x[tid] = xs[tid];

        {
            int i = 0;
            for (int u = bid; u < 384; u += NCOMP, ++i) {
                int m = u >> 7;
                int jbase = (u & 127) << 3;
                const float* W = (m == 0) ? (Wq + mo) : ((m == 1) ? (Wk + mo) : (Wv + mo));
                const float* B = (m == 0) ? (bq + vo) : ((m == 1) ? (bk + vo) : (bv + vo));
                float v = gemv_unit(W, xs, jbase, red4[i & 1]);
                if (tid < 8) {
                    int j = jbase + tid;
                    float o = v + B[j];
                    if (m == 0) g_q[j] = o;
                    else if (m == 1) {
                        g_knew[j] = o;
                        newc[(kplane + SS - 1) * D + j] = o;
                    } else {
                        g_vnew[j] = o;
                        newc[(vplane + SS - 1) * D + j] = o;
                    }
                }
            }
        }
        comp_sync();

        // ===== Phase B: fused scores + softmax(exp, fixed max=0) + A·V =====
        {
            int r = tid >> 8, e = tid & 255, lane = tid & 31;
            float4 q4 = ((const float4*)g_q)[e];
            int s0 = bid << 6;                        // 64 rows per block
            const float4* o4 = (const float4*)oldc;
            float4 Kb0, Vb0, Kb1, Vb1;
#define FETCH_KV(Kv, Vv, g) { int s_ = s0 + ((g) << 2) + r;                         \
            if (s_ < SS - 1) { Kv = o4[(kplane + s_ + 1) * 256 + e];                \
                               Vv = o4[(vplane + s_ + 1) * 256 + e]; }              \
            else { Kv = ((const float4*)g_knew)[e]; Vv = ((const float4*)g_vnew)[e]; } }
            FETCH_KV(Kb0, Vb0, 0);
            FETCH_KV(Kb1, Vb1, 1);
            float accs = 0.f;
            float4 acc = make_float4(0.f, 0.f, 0.f, 0.f);
#pragma unroll
            for (int g = 0; g < 16; ++g) {
                float4 Kc = (g & 1) ? Kb1 : Kb0;
                float4 Vc = (g & 1) ? Vb1 : Vb0;
                if (g + 2 < 16) {
                    if (g & 1) { FETCH_KV(Kb1, Vb1, g + 2); }
                    else       { FETCH_KV(Kb0, Vb0, g + 2); }
                }
                int nz = (Vc.x != 0.f) || (Vc.y != 0.f) || (Vc.z != 0.f) || (Vc.w != 0.f);
                unsigned bal = __ballot_sync(0xffffffffu, nz);
                if (lane == 0) flags[g & 1][tid >> 5] = (bal != 0u);
                __syncthreads();
                int f = 0;
#pragma unroll
                for (int w = 0; w < 8; ++w) f |= flags[g & 1][(r << 3) + w];
                float pd = q4.x * Kc.x + q4.y * Kc.y + q4.z * Kc.z + q4.w * Kc.w;
                pd += __shfl_down_sync(0xffffffffu, pd, 8, 16);
                pd += __shfl_down_sync(0xffffffffu, pd, 4, 16);
                pd += __shfl_down_sync(0xffffffffu, pd, 2, 16);
                pd += __shfl_down_sync(0xffffffffu, pd, 1, 16);
                pd = __shfl_sync(0xffffffffu, pd, lane & 16);
                float p = f ? __expf(pd * 0.125f) : 0.f;   // fixed max = 0
                accs += p;
                acc.x += p * Vc.x; acc.y += p * Vc.y;
                acc.z += p * Vc.z; acc.w += p * Vc.w;
            }
#undef FETCH_KV
            accbuf[r][e] = acc;
            if ((e & 15) == 0) sbuf[r][e >> 4] = accs;
            __syncthreads();
            if (tid < 256) {
                float4 a0 = accbuf[0][tid], a1 = accbuf[1][tid];
                float4 a2 = accbuf[2][tid], a3 = accbuf[3][tid];
                float4 y;
                y.x = a0.x + a1.x + a2.x + a3.x;
                y.y = a0.y + a1.y + a2.y + a3.y;
                y.z = a0.z + a1.z + a2.z + a3.z;
                y.w = a0.w + a1.w + a2.w + a3.w;
                ((float4*)g_avp)[(bid << 8) + tid] = y;
                if ((tid & 15) == 0)
                    g_s[((tid >> 4) << 6) + bid] =
                        sbuf[0][tid >> 4] + sbuf[1][tid >> 4] + sbuf[2][tid >> 4] + sbuf[3][tid >> 4];
            }
        }
        comp_sync();

        // ===== Phase D: combine AV partials (normalize) + Wo GEMV =====
        {
            int c4 = tid >> 8, e = tid & 255;
            const float4* av4 = (const float4*)g_avp;
            float4 a = make_float4(0.f, 0.f, 0.f, 0.f);
#pragma unroll
            for (int c = c4; c < NCOMP; c += 4) {
                float4 p4 = av4[(c << 8) + e];
                a.x += p4.x; a.y += p4.y; a.z += p4.z; a.w += p4.w;
            }
            accbuf[c4][e] = a;
            __syncthreads();
            if (tid < 256) {
                float4 a0 = accbuf[0][tid], a1 = accbuf[1][tid];
                float4 a2 = accbuf[2][tid], a3 = accbuf[3][tid];
                int h = tid >> 4;
                float S = 0.f;
#pragma unroll
                for (int c = 0; c < NCOMP; ++c) S += g_s[(h << 6) + c];
                float is = 1.f / S;
                float4 y;
                y.x = (a0.x + a1.x + a2.x + a3.x) * is;
                y.y = (a0.y + a1.y + a2.y + a3.y) * is;
                y.z = (a0.z + a1.z + a2.z + a3.z) * is;
                y.w = (a0.w + a1.w + a2.w + a3.w) * is;
                ((float4*)xs)[tid] = y;
            }
            __syncthreads();
            int i = 0;
            for (int u = bid; u < 128; u += NCOMP, ++i) {
                int jbase = u << 3;
                float v = gemv_unit(Wo + mo, xs, jbase, red4[i & 1]);
                if (tid < 8) g_attnout[jbase + tid] = v + bo[vo + jbase + tid];
            }
        }
        comp_sync();

        // ===== Phase E: LN1(x + attnout) -> xmid; ff1 GEMV (relu) =====
        {
            float a = g_x[tid] + g_attnout[tid];
            xs[tid] = ln_elem(a, ln1s[vo + tid], ln1b[vo + tid], red);
            __syncthreads();
            if (bid == 0) g_xmid[tid] = xs[tid];
            int i = 0;
            for (int u = bid; u < 128; u += NCOMP, ++i) {
                int jbase = u << 3;
                float v = gemv_unit(Wf1 + mo, xs, jbase, red4[i & 1]);
                if (tid < 8) g_h1[jbase + tid] = fmaxf(v + bf1[vo + jbase + tid], 0.f);
            }
        }
        comp_sync();

        // ===== Phase F: ff2 GEMV =====
        {
            xs[tid] = g_h1[tid];
            __syncthreads();
            int i = 0;
            for (int u = bid; u < 128; u += NCOMP, ++i) {
                int jbase = u << 3;
                float v = gemv_unit(Wf2 + mo, xs, jbase, red4[i & 1]);
                if (tid < 8) g_ffout[jbase + tid] = v + bf2[vo + jbase + tid];
            }
        }
        comp_sync();
    }

    // ===== Final: LN2(last) -> out x; 3 output heads (block 0 only) =====
    if (bid == 0) {
        size_t vo = (size_t)(NL - 1) * D;
        float a = g_xmid[tid] + g_ffout[tid];
        float xv = ln_elem(a, ln2s[vo + tid], ln2b[vo + tid], red);
        xs[tid] = xv;
        __syncthreads();
        out[tid] = xv;
        int w = tid >> 5, lane = tid & 31;
        for (int j = w; j < NHEAD_OUT; j += 32) {
            const float* W; const float* BB; int col, N;
            if (j < 32)      { W = Wpi; BB = bpi; col = j;      N = 32; }
            else if (j < 39) { W = Wvh; BB = bvh; col = j - 32; N = 7;  }
            else             { W = Wc;  BB = bc;  col = j - 39; N = 8;  }
            float acc = 0.f;
            for (int i = lane; i < D; i += 32) acc += xs[i] * W[(size_t)i * N + col];
            acc = warpReduceSum(acc);
            if (lane == 0) out[D + j] = acc + BB[col];
        }
    }
}

extern "C" void kernel_launch(void* const* d_in, const int* in_sizes, int n_in,
                              void* d_out, int out_size) {
    const float* x    = (const float*)d_in[0];
    const float* cach = (const float*)d_in[1];
    const float* Wv   = (const float*)d_in[2];
    const float* bv   = (const float*)d_in[3];
    const float* Wq   = (const float*)d_in[4];
    const float* bq   = (const float*)d_in[5];
    const float* Wk   = (const float*)d_in[6];
    const float* bk   = (const float*)d_in[7];
    const float* Wo   = (const float*)d_in[8];
    const float* bo   = (const float*)d_in[9];
    const float* ln1s = (const float*)d_in[10];
    const float* ln1b = (const float*)d_in[11];
    const float* ln2s = (const float*)d_in[12];
    const float* ln2b = (const float*)d_in[13];
    const float* Wf1  = (const float*)d_in[14];
    const float* bf1  = (const float*)d_in[15];
    const float* Wf2  = (const float*)d_in[16];
    const float* bf2  = (const float*)d_in[17];
    const float* Wpi  = (const float*)d_in[18];
    const float* bpi  = (const float*)d_in[19];
    const float* Wvh  = (const float*)d_in[20];
    const float* bvh  = (const float*)d_in[21];
    const float* Wc   = (const float*)d_in[22];
    const float* bc   = (const float*)d_in[23];

    float* out  = (float*)d_out;
    float* newc = out + (D + NHEAD_OUT);   // cache region of flattened output tuple

    mono_kernel<<<NBLK, 1024>>>(x, cach, Wv, bv, Wq, bq, Wk, bk, Wo, bo,
                                ln1s, ln1b, ln2s, ln2b, Wf1, bf1, Wf2, bf2,
                                Wpi, bpi, Wvh, bvh, Wc, bc, out, newc);
}